// round 2
// baseline (speedup 1.0000x reference)
#include <cuda_runtime.h>
#include <math.h>

#define BB 64
#define HH 1024
#define BH (BB*HH)                       // 65536

// d_out layout: [c_new (B*H*H)][n_new (B*H)][m_new (B)][h (B*H)]
#define OFF_N  ((size_t)BB*(size_t)HH*(size_t)HH)
#define OFF_M  (OFF_N + (size_t)BH)
#define OFF_H  (OFF_M + (size_t)BB)

// scratch (no allocations allowed -> device globals)
__device__ __align__(16) float g_qk[BH];
__device__ float g_ig[BB];
__device__ float g_fg[BB];
__device__ float g_scaler[BB];
__device__ __align__(16) float g_part[2 * 5 * BH];   // split-K partials
__device__ __align__(16) float g_act[5 * BH];        // 0=query 1=key 2=value 3=out 4=skip

// ---------------------------------------------------------------------------
// Kernel A: conv+silu -> qk ; gate scalars i_g, f_g, m_new
// grid: (64), block: 256
// ---------------------------------------------------------------------------
__global__ void kA(const float* __restrict__ x, const float* __restrict__ m,
                   const float* __restrict__ cw, const float* __restrict__ cb,
                   const float* __restrict__ Wi, const float* __restrict__ bi,
                   const float* __restrict__ Wf, const float* __restrict__ bf,
                   float* __restrict__ m_out)
{
    __shared__ float xs[HH];
    __shared__ float si[8], sf[8];
    int b = blockIdx.x, t = threadIdx.x;

    ((float4*)xs)[t] = ((const float4*)(x + b * HH))[t];
    __syncthreads();

    float c0 = cw[0], c1 = cw[1], c2 = cw[2], c3 = cw[3], cbv = cb[0];
    float pi = 0.f, pf = 0.f;
#pragma unroll
    for (int j = 0; j < 4; j++) {
        int w = t * 4 + j;
        // SAME pad for K=4: pad_lo=1, pad_hi=2 ; correlation (no flip)
        float v = cbv + xs[w] * c1;
        if (w >= 1)      v += xs[w - 1] * c0;
        if (w + 1 < HH)  v += xs[w + 1] * c2;
        if (w + 2 < HH)  v += xs[w + 2] * c3;
        float s = v / (1.f + expf(-v));   // silu
        g_qk[b * HH + w] = s;
        pi += xs[w] * Wi[w];
        pf += xs[w] * Wf[w];
    }
#pragma unroll
    for (int o = 16; o; o >>= 1) {
        pi += __shfl_down_sync(~0u, pi, o);
        pf += __shfl_down_sync(~0u, pf, o);
    }
    if ((t & 31) == 0) { si[t >> 5] = pi; sf[t >> 5] = pf; }
    __syncthreads();
    if (t == 0) {
        float it = bi[0], ft = bf[0];
#pragma unroll
        for (int w = 0; w < 8; w++) { it += si[w]; ft += sf[w]; }
        float mb = m[b];
        float mn = fmaxf(ft + mb, it);
        g_ig[b] = expf(it - mn);
        g_fg[b] = expf(ft + mb - mn);
        m_out[b] = mn;
    }
}

// ---------------------------------------------------------------------------
// Kernel B: 5 GEMMs (64x1024 @ 1024x1024), split-K=2, partial sums to g_part.
// BM=64 (=B), BN=64, BK=32. 256 threads, 4x4 register tile per thread.
// grid: (16, 2, 5) = 160 blocks
// ---------------------------------------------------------------------------
__global__ void kGEMM(const float* __restrict__ x,
                      const float* __restrict__ Wq, const float* __restrict__ Wk,
                      const float* __restrict__ Wv, const float* __restrict__ Wo,
                      const float* __restrict__ Ws)
{
    const int z = blockIdx.z, kz = blockIdx.y;
    const float* A = (z == 2 || z == 3) ? x : g_qk;
    const float* W = (z == 0) ? Wq : (z == 1) ? Wk : (z == 2) ? Wv : (z == 3) ? Wo : Ws;
    const int nt = blockIdx.x * 64;
    const int t  = threadIdx.x;
    const int c0 = (t & 15) * 4;
    const int r0 = (t >> 4) * 4;

    // pad = 4 floats: keeps float4 reads 16B-aligned (stride 68*4 bytes)
    __shared__ float As[32][68];
    __shared__ float Bs[32][64];

    float acc[4][4] = {};

    const int kend = kz * 512 + 512;
    for (int kt = kz * 512; kt < kend; kt += 32) {
#pragma unroll
        for (int i = 0; i < 2; i++) {
            int f = t + i * 256;
            int row = f >> 3, kc = (f & 7) * 4;
            float4 v = *(const float4*)(A + row * HH + kt + kc);
            As[kc + 0][row] = v.x; As[kc + 1][row] = v.y;
            As[kc + 2][row] = v.z; As[kc + 3][row] = v.w;
        }
#pragma unroll
        for (int i = 0; i < 2; i++) {
            int f = t + i * 256;
            int kr = f >> 4, nc = (f & 15) * 4;
            *(float4*)&Bs[kr][nc] = *(const float4*)(W + (size_t)(kt + kr) * HH + nt + nc);
        }
        __syncthreads();
#pragma unroll
        for (int k = 0; k < 32; k++) {
            float4 a4 = *(float4*)&As[k][r0];
            float4 b4 = *(float4*)&Bs[k][c0];
            float av[4] = {a4.x, a4.y, a4.z, a4.w};
            float bv[4] = {b4.x, b4.y, b4.z, b4.w};
#pragma unroll
            for (int r = 0; r < 4; r++)
#pragma unroll
                for (int cc = 0; cc < 4; cc++)
                    acc[r][cc] += av[r] * bv[cc];
        }
        __syncthreads();
    }

    float* P = g_part + (size_t)(kz * 5 + z) * BH;
#pragma unroll
    for (int r = 0; r < 4; r++) {
        float4 v = make_float4(acc[r][0], acc[r][1], acc[r][2], acc[r][3]);
        *(float4*)(P + (r0 + r) * HH + nt + c0) = v;
    }
}

// ---------------------------------------------------------------------------
// Epilogue: sum split-K partials, add bias, apply per-matrix activation.
// grid: (5*BH/256)=1280, block 256
// ---------------------------------------------------------------------------
__global__ void kEpi(const float* __restrict__ bq, const float* __restrict__ bk,
                     const float* __restrict__ bv, const float* __restrict__ bo,
                     const float* __restrict__ bs)
{
    int idx = blockIdx.x * 256 + threadIdx.x;
    int z = idx >> 16;          // / BH
    int i = idx & (BH - 1);
    int col = i & (HH - 1);
    const float* bias = (z == 0) ? bq : (z == 1) ? bk : (z == 2) ? bv : (z == 3) ? bo : bs;
    float v = g_part[(size_t)z * BH + i] + g_part[(size_t)(5 + z) * BH + i] + bias[col];
    if (z == 1) v *= 0.03125f;                 // key / sqrt(H)
    if (z == 3) v = 1.f / (1.f + expf(-v));    // sigmoid(out)
    g_act[(size_t)z * BH + i] = v;
}

// ---------------------------------------------------------------------------
// Kernel C: n_new = f_g*n + i_g*key (write to d_out), scaler = 1/max(|n_new.q|,1)
// grid: (64), block 256
// ---------------------------------------------------------------------------
__global__ void kC(const float* __restrict__ n, float* __restrict__ out)
{
    __shared__ float sred[8];
    int b = blockIdx.x, t = threadIdx.x;
    float fg = g_fg[b], ig = g_ig[b];
    float4 n4 = ((const float4*)(n + b * HH))[t];
    float4 k4 = ((const float4*)(g_act + 1 * BH + b * HH))[t];
    float4 q4 = ((const float4*)(g_act + 0 * BH + b * HH))[t];
    float4 nn;
    nn.x = fg * n4.x + ig * k4.x;
    nn.y = fg * n4.y + ig * k4.y;
    nn.z = fg * n4.z + ig * k4.z;
    nn.w = fg * n4.w + ig * k4.w;
    ((float4*)(out + OFF_N + (size_t)b * HH))[t] = nn;
    float p = nn.x * q4.x + nn.y * q4.y + nn.z * q4.z + nn.w * q4.w;
#pragma unroll
    for (int o = 16; o; o >>= 1) p += __shfl_down_sync(~0u, p, o);
    if ((t & 31) == 0) sred[t >> 5] = p;
    __syncthreads();
    if (t == 0) {
        float s = 0.f;
#pragma unroll
        for (int w = 0; w < 8; w++) s += sred[w];
        s = fabsf(s);
        g_scaler[b] = 1.f / fmaxf(s, 1.f);
    }
}

// ---------------------------------------------------------------------------
// Kernel D: the HBM-bound pass. c_new = f_g*c + (i_g*v_i)*k ; fused
// h_i = out_i * (sum_k c_new*q) * scaler + skip_i.
// grid: (64 rowblocks, 64 batches), block 256 (8 warps, 2 rows/warp)
// ---------------------------------------------------------------------------
__global__ void kD(const float* __restrict__ c, float* __restrict__ out)
{
    __shared__ float ks[HH];
    __shared__ float qs[HH];
    int rb = blockIdx.x, b = blockIdx.y;
    int t = threadIdx.x, lane = t & 31, wid = t >> 5;

    ((float4*)ks)[t] = ((const float4*)(g_act + 1 * BH + b * HH))[t];
    ((float4*)qs)[t] = ((const float4*)(g_act + 0 * BH + b * HH))[t];
    __syncthreads();

    float fg = g_fg[b], ig = g_ig[b], sc = g_scaler[b];

#pragma unroll
    for (int rr = 0; rr < 2; rr++) {
        int i = rb * 16 + wid * 2 + rr;
        size_t base = ((size_t)b * HH + i) * (size_t)HH;
        const float* crow = c + base;
        float* cn = out + base;                       // c_new at offset 0
        float igv = ig * g_act[2 * BH + b * HH + i];
        float acc = 0.f;
#pragma unroll
        for (int ch = 0; ch < 8; ch++) {
            int k0 = ch * 128 + lane * 4;
            float4 cv = *(const float4*)(crow + k0);
            float4 kk = *(const float4*)(ks + k0);
            float4 qq = *(const float4*)(qs + k0);
            float4 r;
            r.x = fg * cv.x + igv * kk.x;
            r.y = fg * cv.y + igv * kk.y;
            r.z = fg * cv.z + igv * kk.z;
            r.w = fg * cv.w + igv * kk.w;
            *(float4*)(cn + k0) = r;
            acc += r.x * qq.x + r.y * qq.y + r.z * qq.z + r.w * qq.w;
        }
#pragma unroll
        for (int o = 16; o; o >>= 1) acc += __shfl_xor_sync(~0u, acc, o);
        if (lane == 0) {
            float h = g_act[3 * BH + b * HH + i] * (acc * sc) + g_act[4 * BH + b * HH + i];
            out[OFF_H + (size_t)b * HH + i] = h;
        }
    }
}

// ---------------------------------------------------------------------------
extern "C" void kernel_launch(void* const* d_in, const int* in_sizes, int n_in,
                              void* d_out, int out_size)
{
    (void)in_sizes; (void)n_in; (void)out_size;
    const float* c      = (const float*)d_in[0];
    const float* n      = (const float*)d_in[1];
    const float* m      = (const float*)d_in[2];
    const float* x      = (const float*)d_in[3];
    const float* Wq     = (const float*)d_in[4];
    const float* bq     = (const float*)d_in[5];
    const float* Wk     = (const float*)d_in[6];
    const float* bk     = (const float*)d_in[7];
    const float* Wv     = (const float*)d_in[8];
    const float* bv     = (const float*)d_in[9];
    const float* conv_w = (const float*)d_in[10];
    const float* conv_b = (const float*)d_in[11];
    const float* Wi     = (const float*)d_in[12];
    const float* bi     = (const float*)d_in[13];
    const float* Wf     = (const float*)d_in[14];
    const float* bf     = (const float*)d_in[15];
    const float* Wo     = (const float*)d_in[16];
    const float* bo     = (const float*)d_in[17];
    const float* Wskip  = (const float*)d_in[18];
    const float* bskip  = (const float*)d_in[19];
    float* out = (float*)d_out;

    kA<<<BB, 256>>>(x, m, conv_w, conv_b, Wi, bi, Wf, bf, out + OFF_M);
    kGEMM<<<dim3(16, 2, 5), 256>>>(x, Wq, Wk, Wv, Wo, Wskip);
    kEpi<<<(5 * BH) / 256, 256>>>(bq, bk, bv, bo, bskip);
    kC<<<BB, 256>>>(n, out);
    kD<<<dim3(64, 64), 256>>>(c, out);
}

// round 3
// speedup vs baseline: 1.0584x; 1.0584x over previous
#include <cuda_runtime.h>
#include <math.h>

#define BB 64
#define HH 1024
#define BH (BB*HH)                       // 65536

// d_out layout: [c_new (B*H*H)][n_new (B*H)][m_new (B)][h (B*H)]
#define OFF_N  ((size_t)BB*(size_t)HH*(size_t)HH)
#define OFF_M  (OFF_N + (size_t)BH)
#define OFF_H  (OFF_M + (size_t)BB)

// scratch (no allocations allowed -> device globals)
__device__ __align__(16) float g_qk[BH];
__device__ float g_ig[BB];
__device__ float g_fg[BB];
__device__ __align__(16) float g_part[4 * 5 * BH];   // split-K=4 partials
__device__ __align__(16) float g_act[5 * BH];        // 0=query 1=key 2=value 3=out 4=skip

// ---------------------------------------------------------------------------
// Kernel A: conv+silu -> qk ; gate scalars i_g, f_g, m_new
// ---------------------------------------------------------------------------
__global__ void kA(const float* __restrict__ x, const float* __restrict__ m,
                   const float* __restrict__ cw, const float* __restrict__ cb,
                   const float* __restrict__ Wi, const float* __restrict__ bi,
                   const float* __restrict__ Wf, const float* __restrict__ bf,
                   float* __restrict__ m_out)
{
    __shared__ float xs[HH];
    __shared__ float si[8], sf[8];
    int b = blockIdx.x, t = threadIdx.x;

    ((float4*)xs)[t] = ((const float4*)(x + b * HH))[t];
    __syncthreads();

    float c0 = cw[0], c1 = cw[1], c2 = cw[2], c3 = cw[3], cbv = cb[0];
    float pi = 0.f, pf = 0.f;
#pragma unroll
    for (int j = 0; j < 4; j++) {
        int w = t * 4 + j;
        // SAME pad for K=4: pad_lo=1, pad_hi=2 ; correlation (no flip)
        float v = cbv + xs[w] * c1;
        if (w >= 1)      v += xs[w - 1] * c0;
        if (w + 1 < HH)  v += xs[w + 1] * c2;
        if (w + 2 < HH)  v += xs[w + 2] * c3;
        float s = v / (1.f + expf(-v));   // silu
        g_qk[b * HH + w] = s;
        pi += xs[w] * Wi[w];
        pf += xs[w] * Wf[w];
    }
#pragma unroll
    for (int o = 16; o; o >>= 1) {
        pi += __shfl_down_sync(~0u, pi, o);
        pf += __shfl_down_sync(~0u, pf, o);
    }
    if ((t & 31) == 0) { si[t >> 5] = pi; sf[t >> 5] = pf; }
    __syncthreads();
    if (t == 0) {
        float it = bi[0], ft = bf[0];
#pragma unroll
        for (int w = 0; w < 8; w++) { it += si[w]; ft += sf[w]; }
        float mb = m[b];
        float mn = fmaxf(ft + mb, it);
        g_ig[b] = expf(it - mn);
        g_fg[b] = expf(ft + mb - mn);
        m_out[b] = mn;
    }
}

// ---------------------------------------------------------------------------
// Kernel B: 5 GEMMs (64x1024 @ 1024x1024), split-K=4, BM=64 BN=128 BK=32.
// 128 threads, 8x8 register tile (2x2 blocks of 4x4 -> contiguous LDS.128).
// grid: (8, 4, 5) = 160 blocks
// ---------------------------------------------------------------------------
__global__ void kGEMM(const float* __restrict__ x,
                      const float* __restrict__ Wq, const float* __restrict__ Wk,
                      const float* __restrict__ Wv, const float* __restrict__ Wo,
                      const float* __restrict__ Ws)
{
    const int z = blockIdx.z, kz = blockIdx.y;
    const float* A = (z == 2 || z == 3) ? x : g_qk;
    const float* W = (z == 0) ? Wq : (z == 1) ? Wk : (z == 2) ? Wv : (z == 3) ? Wo : Ws;
    const int nt = blockIdx.x * 128;
    const int t  = threadIdx.x;          // 128 threads
    const int ra = (t >> 4) * 4;         // row group base: 0..28
    const int cbx = (t & 15) * 4;        // col group base: 0..60

    __shared__ float As[32][68];         // [k][row], pad 4 keeps float4 aligned
    __shared__ float Bs[32][128];        // [k][col]

    float4 acc[2][2][4];
#pragma unroll
    for (int ih = 0; ih < 2; ih++)
#pragma unroll
        for (int jh = 0; jh < 2; jh++)
#pragma unroll
            for (int r = 0; r < 4; r++)
                acc[ih][jh][r] = make_float4(0.f, 0.f, 0.f, 0.f);

    const int kbeg = kz * 256, kend = kbeg + 256;
    for (int kt = kbeg; kt < kend; kt += 32) {
#pragma unroll
        for (int i = 0; i < 4; i++) {    // A: 64x32 = 512 float4 / 128 thr
            int f = t + i * 128;
            int row = f >> 3, kc = (f & 7) * 4;
            float4 v = *(const float4*)(A + row * HH + kt + kc);
            As[kc + 0][row] = v.x; As[kc + 1][row] = v.y;
            As[kc + 2][row] = v.z; As[kc + 3][row] = v.w;
        }
#pragma unroll
        for (int i = 0; i < 8; i++) {    // B: 32x128 = 1024 float4 / 128 thr
            int f = t + i * 128;
            int kr = f >> 5, nc = (f & 31) * 4;
            *(float4*)&Bs[kr][nc] = *(const float4*)(W + (size_t)(kt + kr) * HH + nt + nc);
        }
        __syncthreads();
#pragma unroll
        for (int k = 0; k < 32; k++) {
            float4 a0 = *(float4*)&As[k][ra];
            float4 a1 = *(float4*)&As[k][32 + ra];
            float4 b0 = *(float4*)&Bs[k][cbx];
            float4 b1 = *(float4*)&Bs[k][64 + cbx];
            float av0[4] = {a0.x, a0.y, a0.z, a0.w};
            float av1[4] = {a1.x, a1.y, a1.z, a1.w};
#pragma unroll
            for (int r = 0; r < 4; r++) {
                acc[0][0][r].x += av0[r] * b0.x; acc[0][0][r].y += av0[r] * b0.y;
                acc[0][0][r].z += av0[r] * b0.z; acc[0][0][r].w += av0[r] * b0.w;
                acc[0][1][r].x += av0[r] * b1.x; acc[0][1][r].y += av0[r] * b1.y;
                acc[0][1][r].z += av0[r] * b1.z; acc[0][1][r].w += av0[r] * b1.w;
                acc[1][0][r].x += av1[r] * b0.x; acc[1][0][r].y += av1[r] * b0.y;
                acc[1][0][r].z += av1[r] * b0.z; acc[1][0][r].w += av1[r] * b0.w;
                acc[1][1][r].x += av1[r] * b1.x; acc[1][1][r].y += av1[r] * b1.y;
                acc[1][1][r].z += av1[r] * b1.z; acc[1][1][r].w += av1[r] * b1.w;
            }
        }
        __syncthreads();
    }

    float* P = g_part + (size_t)(kz * 5 + z) * BH;
#pragma unroll
    for (int ih = 0; ih < 2; ih++)
#pragma unroll
        for (int r = 0; r < 4; r++) {
            int row = ih * 32 + ra + r;
#pragma unroll
            for (int jh = 0; jh < 2; jh++)
                *(float4*)(P + row * HH + nt + jh * 64 + cbx) = acc[ih][jh][r];
        }
}

// ---------------------------------------------------------------------------
// Epilogue: sum 4 split-K partials + bias + activation -> g_act.
// z==1 (key) lanes also write n_new = f_g*n + i_g*key to d_out.
// grid: 5*BH/4/256 = 320 blocks
// ---------------------------------------------------------------------------
__global__ void kEpi(const float* __restrict__ bq, const float* __restrict__ bk,
                     const float* __restrict__ bv, const float* __restrict__ bo,
                     const float* __restrict__ bs,
                     const float* __restrict__ n, float* __restrict__ out)
{
    int idx = blockIdx.x * 256 + threadIdx.x;   // float4 index
    int e = idx * 4;
    int z = e >> 16;
    int i = e & (BH - 1);
    int col = i & (HH - 1);
    int b = i >> 10;
    const float* bias = (z == 0) ? bq : (z == 1) ? bk : (z == 2) ? bv : (z == 3) ? bo : bs;

    float4 v = *(const float4*)(g_part + (size_t)z * BH + i);
    float4 p1 = *(const float4*)(g_part + (size_t)(5 + z) * BH + i);
    float4 p2 = *(const float4*)(g_part + (size_t)(10 + z) * BH + i);
    float4 p3 = *(const float4*)(g_part + (size_t)(15 + z) * BH + i);
    float4 bb = *(const float4*)(bias + col);
    v.x += p1.x + p2.x + p3.x + bb.x;
    v.y += p1.y + p2.y + p3.y + bb.y;
    v.z += p1.z + p2.z + p3.z + bb.z;
    v.w += p1.w + p2.w + p3.w + bb.w;
    if (z == 1) { v.x *= 0.03125f; v.y *= 0.03125f; v.z *= 0.03125f; v.w *= 0.03125f; }
    if (z == 3) {
        v.x = 1.f / (1.f + expf(-v.x)); v.y = 1.f / (1.f + expf(-v.y));
        v.z = 1.f / (1.f + expf(-v.z)); v.w = 1.f / (1.f + expf(-v.w));
    }
    *(float4*)(g_act + (size_t)z * BH + i) = v;

    if (z == 1) {
        float fg = g_fg[b], ig = g_ig[b];
        float4 n4 = *(const float4*)(n + i);
        float4 nn;
        nn.x = fg * n4.x + ig * v.x;
        nn.y = fg * n4.y + ig * v.y;
        nn.z = fg * n4.z + ig * v.z;
        nn.w = fg * n4.w + ig * v.w;
        *(float4*)(out + OFF_N + i) = nn;
    }
}

// ---------------------------------------------------------------------------
// Kernel D: HBM-bound pass. Computes scaler locally (deterministic, identical
// in all blocks of a batch): n_new.q = f_g*(n.q) + i_g*(k.q).
// c_new = f_g*c + (i_g*v_i)*k ; h_i = out_i*(c_new_i.q)*scaler + skip_i.
// grid: (64 rowblocks, 64 batches), block 256
// ---------------------------------------------------------------------------
__global__ void kD(const float* __restrict__ c, const float* __restrict__ n,
                   float* __restrict__ out)
{
    __shared__ float ks[HH];
    __shared__ float qs[HH];
    __shared__ float red[16];
    int rb = blockIdx.x, b = blockIdx.y;
    int t = threadIdx.x, lane = t & 31, wid = t >> 5;

    float4 k4 = ((const float4*)(g_act + 1 * BH + b * HH))[t];
    float4 q4 = ((const float4*)(g_act + 0 * BH + b * HH))[t];
    float4 n4 = ((const float4*)(n + b * HH))[t];
    ((float4*)ks)[t] = k4;
    ((float4*)qs)[t] = q4;
    float pkq = k4.x * q4.x + k4.y * q4.y + k4.z * q4.z + k4.w * q4.w;
    float pnq = n4.x * q4.x + n4.y * q4.y + n4.z * q4.z + n4.w * q4.w;
#pragma unroll
    for (int o = 16; o; o >>= 1) {
        pkq += __shfl_xor_sync(~0u, pkq, o);
        pnq += __shfl_xor_sync(~0u, pnq, o);
    }
    if (lane == 0) { red[wid] = pkq; red[8 + wid] = pnq; }
    __syncthreads();

    float kq = 0.f, nq = 0.f;
#pragma unroll
    for (int w = 0; w < 8; w++) { kq += red[w]; nq += red[8 + w]; }
    float fg = g_fg[b], ig = g_ig[b];
    float sc = 1.f / fmaxf(fabsf(fg * nq + ig * kq), 1.f);

#pragma unroll
    for (int rr = 0; rr < 2; rr++) {
        int i = rb * 16 + wid * 2 + rr;
        size_t base = ((size_t)b * HH + i) * (size_t)HH;
        const float* crow = c + base;
        float* cn = out + base;                       // c_new at offset 0
        float igv = ig * g_act[2 * BH + b * HH + i];
        float acc = 0.f;
#pragma unroll
        for (int ch = 0; ch < 8; ch++) {
            int k0 = ch * 128 + lane * 4;
            float4 cv = *(const float4*)(crow + k0);
            float4 kk = *(const float4*)(ks + k0);
            float4 qq = *(const float4*)(qs + k0);
            float4 r;
            r.x = fg * cv.x + igv * kk.x;
            r.y = fg * cv.y + igv * kk.y;
            r.z = fg * cv.z + igv * kk.z;
            r.w = fg * cv.w + igv * kk.w;
            *(float4*)(cn + k0) = r;
            acc += r.x * qq.x + r.y * qq.y + r.z * qq.z + r.w * qq.w;
        }
#pragma unroll
        for (int o = 16; o; o >>= 1) acc += __shfl_xor_sync(~0u, acc, o);
        if (lane == 0) {
            float h = g_act[3 * BH + b * HH + i] * (acc * sc) + g_act[4 * BH + b * HH + i];
            out[OFF_H + (size_t)b * HH + i] = h;
        }
    }
}

// ---------------------------------------------------------------------------
extern "C" void kernel_launch(void* const* d_in, const int* in_sizes, int n_in,
                              void* d_out, int out_size)
{
    (void)in_sizes; (void)n_in; (void)out_size;
    const float* c      = (const float*)d_in[0];
    const float* n      = (const float*)d_in[1];
    const float* m      = (const float*)d_in[2];
    const float* x      = (const float*)d_in[3];
    const float* Wq     = (const float*)d_in[4];
    const float* bq     = (const float*)d_in[5];
    const float* Wk     = (const float*)d_in[6];
    const float* bk     = (const float*)d_in[7];
    const float* Wv     = (const float*)d_in[8];
    const float* bv     = (const float*)d_in[9];
    const float* conv_w = (const float*)d_in[10];
    const float* conv_b = (const float*)d_in[11];
    const float* Wi     = (const float*)d_in[12];
    const float* bi     = (const float*)d_in[13];
    const float* Wf     = (const float*)d_in[14];
    const float* bf     = (const float*)d_in[15];
    const float* Wo     = (const float*)d_in[16];
    const float* bo     = (const float*)d_in[17];
    const float* Wskip  = (const float*)d_in[18];
    const float* bskip  = (const float*)d_in[19];
    float* out = (float*)d_out;

    kA<<<BB, 256>>>(x, m, conv_w, conv_b, Wi, bi, Wf, bf, out + OFF_M);
    kGEMM<<<dim3(8, 4, 5), 128>>>(x, Wq, Wk, Wv, Wo, Wskip);
    kEpi<<<320, 256>>>(bq, bk, bv, bo, bskip, n, out);
    kD<<<dim3(64, 64), 256>>>(c, n, out);
}

// round 4
// speedup vs baseline: 1.2775x; 1.2070x over previous
#include <cuda_runtime.h>
#include <math.h>

#define BB 64
#define HH 1024
#define BH (BB*HH)                       // 65536
#define SK 8                             // split-K factor

// d_out layout: [c_new (B*H*H)][n_new (B*H)][m_new (B)][h (B*H)]
#define OFF_N  ((size_t)BB*(size_t)HH*(size_t)HH)
#define OFF_M  (OFF_N + (size_t)BH)
#define OFF_H  (OFF_M + (size_t)BB)

// scratch (no allocations allowed -> device globals)
__device__ __align__(16) float g_qk[BH];
__device__ float g_ig[BB];
__device__ float g_fg[BB];
__device__ __align__(16) float g_part[SK * 5 * BH];  // split-K partials
__device__ __align__(16) float g_act[5 * BH];        // 0=query 1=key 2=value 3=out 4=skip

// ---------------------------------------------------------------------------
// Kernel A: conv+silu -> qk ; gate scalars i_g, f_g, m_new
// ---------------------------------------------------------------------------
__global__ void kA(const float* __restrict__ x, const float* __restrict__ m,
                   const float* __restrict__ cw, const float* __restrict__ cb,
                   const float* __restrict__ Wi, const float* __restrict__ bi,
                   const float* __restrict__ Wf, const float* __restrict__ bf,
                   float* __restrict__ m_out)
{
    __shared__ float xs[HH];
    __shared__ float si[8], sf[8];
    int b = blockIdx.x, t = threadIdx.x;

    ((float4*)xs)[t] = ((const float4*)(x + b * HH))[t];
    __syncthreads();

    float c0 = cw[0], c1 = cw[1], c2 = cw[2], c3 = cw[3], cbv = cb[0];
    float pi = 0.f, pf = 0.f;
#pragma unroll
    for (int j = 0; j < 4; j++) {
        int w = t * 4 + j;
        // SAME pad for K=4: pad_lo=1, pad_hi=2 ; correlation (no flip)
        float v = cbv + xs[w] * c1;
        if (w >= 1)      v += xs[w - 1] * c0;
        if (w + 1 < HH)  v += xs[w + 1] * c2;
        if (w + 2 < HH)  v += xs[w + 2] * c3;
        float s = v / (1.f + expf(-v));   // silu
        g_qk[b * HH + w] = s;
        pi += xs[w] * Wi[w];
        pf += xs[w] * Wf[w];
    }
#pragma unroll
    for (int o = 16; o; o >>= 1) {
        pi += __shfl_down_sync(~0u, pi, o);
        pf += __shfl_down_sync(~0u, pf, o);
    }
    if ((t & 31) == 0) { si[t >> 5] = pi; sf[t >> 5] = pf; }
    __syncthreads();
    if (t == 0) {
        float it = bi[0], ft = bf[0];
#pragma unroll
        for (int w = 0; w < 8; w++) { it += si[w]; ft += sf[w]; }
        float mb = m[b];
        float mn = fmaxf(ft + mb, it);
        g_ig[b] = expf(it - mn);
        g_fg[b] = expf(ft + mb - mn);
        m_out[b] = mn;
    }
}

// ---------------------------------------------------------------------------
// Kernel B: 5 GEMMs (64x1024 @ 1024x1024), split-K=8, BM=64 BN=128 BK=32.
// 128 threads, 8x8 register tile. grid: (8, 8, 5) = 320 blocks
// ---------------------------------------------------------------------------
__global__ void kGEMM(const float* __restrict__ x,
                      const float* __restrict__ Wq, const float* __restrict__ Wk,
                      const float* __restrict__ Wv, const float* __restrict__ Wo,
                      const float* __restrict__ Ws)
{
    const int z = blockIdx.z, kz = blockIdx.y;
    const float* A = (z == 2 || z == 3) ? x : g_qk;
    const float* W = (z == 0) ? Wq : (z == 1) ? Wk : (z == 2) ? Wv : (z == 3) ? Wo : Ws;
    const int nt = blockIdx.x * 128;
    const int t  = threadIdx.x;          // 128 threads
    const int ra = (t >> 4) * 4;         // row group base: 0..28
    const int cbx = (t & 15) * 4;        // col group base: 0..60

    __shared__ float As[32][68];         // [k][row], pad 4 keeps float4 aligned
    __shared__ float Bs[32][128];        // [k][col]

    float4 acc[2][2][4];
#pragma unroll
    for (int ih = 0; ih < 2; ih++)
#pragma unroll
        for (int jh = 0; jh < 2; jh++)
#pragma unroll
            for (int r = 0; r < 4; r++)
                acc[ih][jh][r] = make_float4(0.f, 0.f, 0.f, 0.f);

    const int kbeg = kz * (HH / SK), kend = kbeg + (HH / SK);
    for (int kt = kbeg; kt < kend; kt += 32) {
#pragma unroll
        for (int i = 0; i < 4; i++) {    // A: 64x32 = 512 float4 / 128 thr
            int f = t + i * 128;
            int row = f >> 3, kc = (f & 7) * 4;
            float4 v = *(const float4*)(A + row * HH + kt + kc);
            As[kc + 0][row] = v.x; As[kc + 1][row] = v.y;
            As[kc + 2][row] = v.z; As[kc + 3][row] = v.w;
        }
#pragma unroll
        for (int i = 0; i < 8; i++) {    // B: 32x128 = 1024 float4 / 128 thr
            int f = t + i * 128;
            int kr = f >> 5, nc = (f & 31) * 4;
            *(float4*)&Bs[kr][nc] = *(const float4*)(W + (size_t)(kt + kr) * HH + nt + nc);
        }
        __syncthreads();
#pragma unroll
        for (int k = 0; k < 32; k++) {
            float4 a0 = *(float4*)&As[k][ra];
            float4 a1 = *(float4*)&As[k][32 + ra];
            float4 b0 = *(float4*)&Bs[k][cbx];
            float4 b1 = *(float4*)&Bs[k][64 + cbx];
            float av0[4] = {a0.x, a0.y, a0.z, a0.w};
            float av1[4] = {a1.x, a1.y, a1.z, a1.w};
#pragma unroll
            for (int r = 0; r < 4; r++) {
                acc[0][0][r].x += av0[r] * b0.x; acc[0][0][r].y += av0[r] * b0.y;
                acc[0][0][r].z += av0[r] * b0.z; acc[0][0][r].w += av0[r] * b0.w;
                acc[0][1][r].x += av0[r] * b1.x; acc[0][1][r].y += av0[r] * b1.y;
                acc[0][1][r].z += av0[r] * b1.z; acc[0][1][r].w += av0[r] * b1.w;
                acc[1][0][r].x += av1[r] * b0.x; acc[1][0][r].y += av1[r] * b0.y;
                acc[1][0][r].z += av1[r] * b0.z; acc[1][0][r].w += av1[r] * b0.w;
                acc[1][1][r].x += av1[r] * b1.x; acc[1][1][r].y += av1[r] * b1.y;
                acc[1][1][r].z += av1[r] * b1.z; acc[1][1][r].w += av1[r] * b1.w;
            }
        }
        __syncthreads();
    }

    float* P = g_part + (size_t)(kz * 5 + z) * BH;
#pragma unroll
    for (int ih = 0; ih < 2; ih++)
#pragma unroll
        for (int r = 0; r < 4; r++) {
            int row = ih * 32 + ra + r;
#pragma unroll
            for (int jh = 0; jh < 2; jh++)
                *(float4*)(P + row * HH + nt + jh * 64 + cbx) = acc[ih][jh][r];
        }
}

// ---------------------------------------------------------------------------
// Epilogue: sum SK split-K partials + bias + activation -> g_act.
// z==1 (key) lanes also write n_new = f_g*n + i_g*key to d_out.
// grid: 5*BH/4/256 = 320 blocks
// ---------------------------------------------------------------------------
__global__ void kEpi(const float* __restrict__ bq, const float* __restrict__ bk,
                     const float* __restrict__ bv, const float* __restrict__ bo,
                     const float* __restrict__ bs,
                     const float* __restrict__ n, float* __restrict__ out)
{
    int idx = blockIdx.x * 256 + threadIdx.x;   // float4 index
    int e = idx * 4;
    int z = e >> 16;
    int i = e & (BH - 1);
    int col = i & (HH - 1);
    int b = i >> 10;
    const float* bias = (z == 0) ? bq : (z == 1) ? bk : (z == 2) ? bv : (z == 3) ? bo : bs;

    float4 v = *(const float4*)(g_part + (size_t)z * BH + i);
#pragma unroll
    for (int s = 1; s < SK; s++) {
        float4 p = *(const float4*)(g_part + (size_t)(s * 5 + z) * BH + i);
        v.x += p.x; v.y += p.y; v.z += p.z; v.w += p.w;
    }
    float4 bb = *(const float4*)(bias + col);
    v.x += bb.x; v.y += bb.y; v.z += bb.z; v.w += bb.w;
    if (z == 1) { v.x *= 0.03125f; v.y *= 0.03125f; v.z *= 0.03125f; v.w *= 0.03125f; }
    if (z == 3) {
        v.x = 1.f / (1.f + expf(-v.x)); v.y = 1.f / (1.f + expf(-v.y));
        v.z = 1.f / (1.f + expf(-v.z)); v.w = 1.f / (1.f + expf(-v.w));
    }
    *(float4*)(g_act + (size_t)z * BH + i) = v;

    if (z == 1) {
        float fg = g_fg[b], ig = g_ig[b];
        float4 n4 = *(const float4*)(n + i);
        float4 nn;
        nn.x = fg * n4.x + ig * v.x;
        nn.y = fg * n4.y + ig * v.y;
        nn.z = fg * n4.z + ig * v.z;
        nn.w = fg * n4.w + ig * v.w;
        *(float4*)(out + OFF_N + i) = nn;
    }
}

// ---------------------------------------------------------------------------
// Kernel D: HBM-bound pass. One warp per cell row, 8 rows per block.
// scaler computed locally per block: |f_g*(n.q) + i_g*(k.q)|.
// c_new = f_g*c + (i_g*v_i)*k ; h_i = out_i*(c_new_i.q)*scaler + skip_i.
// grid: (128 rowblocks, 64 batches), block 256
// ---------------------------------------------------------------------------
__global__ void __launch_bounds__(256, 4)
kD(const float* __restrict__ c, const float* __restrict__ n,
   float* __restrict__ out)
{
    __shared__ float ks[HH];
    __shared__ float qs[HH];
    __shared__ float red[16];
    int rb = blockIdx.x, b = blockIdx.y;
    int t = threadIdx.x, lane = t & 31, wid = t >> 5;

    float4 k4 = ((const float4*)(g_act + 1 * BH + b * HH))[t];
    float4 q4 = ((const float4*)(g_act + 0 * BH + b * HH))[t];
    float4 n4 = ((const float4*)(n + b * HH))[t];
    ((float4*)ks)[t] = k4;
    ((float4*)qs)[t] = q4;
    float pkq = k4.x * q4.x + k4.y * q4.y + k4.z * q4.z + k4.w * q4.w;
    float pnq = n4.x * q4.x + n4.y * q4.y + n4.z * q4.z + n4.w * q4.w;
#pragma unroll
    for (int o = 16; o; o >>= 1) {
        pkq += __shfl_xor_sync(~0u, pkq, o);
        pnq += __shfl_xor_sync(~0u, pnq, o);
    }
    if (lane == 0) { red[wid] = pkq; red[8 + wid] = pnq; }
    __syncthreads();

    float kq = 0.f, nq = 0.f;
#pragma unroll
    for (int w = 0; w < 8; w++) { kq += red[w]; nq += red[8 + w]; }
    float fg = g_fg[b], ig = g_ig[b];
    float sc = 1.f / fmaxf(fabsf(fg * nq + ig * kq), 1.f);

    const int i = rb * 8 + wid;                       // this warp's row
    const size_t base = ((size_t)b * HH + i) * (size_t)HH;
    const float* crow = c + base;
    float* cn = out + base;                           // c_new at offset 0
    const float igv = ig * g_act[2 * BH + b * HH + i];
    float acc = 0.f;

#pragma unroll
    for (int half = 0; half < 2; half++) {
        float4 cv[4];
#pragma unroll
        for (int j = 0; j < 4; j++)
            cv[j] = __ldcs((const float4*)(crow + (half * 4 + j) * 128 + lane * 4));
#pragma unroll
        for (int j = 0; j < 4; j++) {
            int k0 = (half * 4 + j) * 128 + lane * 4;
            float4 kk = *(float4*)(ks + k0);
            float4 qq = *(float4*)(qs + k0);
            float4 r;
            r.x = fg * cv[j].x + igv * kk.x;
            r.y = fg * cv[j].y + igv * kk.y;
            r.z = fg * cv[j].z + igv * kk.z;
            r.w = fg * cv[j].w + igv * kk.w;
            __stcs((float4*)(cn + k0), r);
            acc += r.x * qq.x + r.y * qq.y + r.z * qq.z + r.w * qq.w;
        }
    }
#pragma unroll
    for (int o = 16; o; o >>= 1) acc += __shfl_xor_sync(~0u, acc, o);
    if (lane == 0) {
        float h = g_act[3 * BH + b * HH + i] * (acc * sc) + g_act[4 * BH + b * HH + i];
        out[OFF_H + (size_t)b * HH + i] = h;
    }
}

// ---------------------------------------------------------------------------
extern "C" void kernel_launch(void* const* d_in, const int* in_sizes, int n_in,
                              void* d_out, int out_size)
{
    (void)in_sizes; (void)n_in; (void)out_size;
    const float* c      = (const float*)d_in[0];
    const float* n      = (const float*)d_in[1];
    const float* m      = (const float*)d_in[2];
    const float* x      = (const float*)d_in[3];
    const float* Wq     = (const float*)d_in[4];
    const float* bq     = (const float*)d_in[5];
    const float* Wk     = (const float*)d_in[6];
    const float* bk     = (const float*)d_in[7];
    const float* Wv     = (const float*)d_in[8];
    const float* bv     = (const float*)d_in[9];
    const float* conv_w = (const float*)d_in[10];
    const float* conv_b = (const float*)d_in[11];
    const float* Wi     = (const float*)d_in[12];
    const float* bi     = (const float*)d_in[13];
    const float* Wf     = (const float*)d_in[14];
    const float* bf     = (const float*)d_in[15];
    const float* Wo     = (const float*)d_in[16];
    const float* bo     = (const float*)d_in[17];
    const float* Wskip  = (const float*)d_in[18];
    const float* bskip  = (const float*)d_in[19];
    float* out = (float*)d_out;

    kA<<<BB, 256>>>(x, m, conv_w, conv_b, Wi, bi, Wf, bf, out + OFF_M);
    kGEMM<<<dim3(8, SK, 5), 128>>>(x, Wq, Wk, Wv, Wo, Wskip);
    kEpi<<<320, 256>>>(bq, bk, bv, bo, bskip, n, out);
    kD<<<dim3(128, 64), 256>>>(c, n, out);
}

// round 5
// speedup vs baseline: 1.3379x; 1.0472x over previous
#include <cuda_runtime.h>
#include <math.h>

#define BB 64
#define HH 1024
#define BH (BB*HH)                       // 65536
#define SK 8                             // split-K factor

// d_out layout: [c_new (B*H*H)][n_new (B*H)][m_new (B)][h (B*H)]
#define OFF_N  ((size_t)BB*(size_t)HH*(size_t)HH)
#define OFF_M  (OFF_N + (size_t)BH)
#define OFF_H  (OFF_M + (size_t)BB)

// scratch (no allocations allowed -> device globals)
__device__ __align__(16) float g_qk[BH];
__device__ float g_ig[BB];
__device__ float g_fg[BB];
__device__ float g_scaler[BB];
__device__ __align__(16) float g_part[SK * 5 * BH];  // split-K partials
__device__ __align__(16) float g_act[5 * BH];        // 0=query 1=key 2=value 3=out 4=skip

__device__ __forceinline__ unsigned f2tf(float f) {
    unsigned u;
    asm("cvt.rna.tf32.f32 %0, %1;" : "=r"(u) : "f"(f));
    return u;
}

__device__ __forceinline__ void mma_tf32(float* d, const unsigned* a, const unsigned* b) {
    asm("mma.sync.aligned.m16n8k8.row.col.f32.tf32.tf32.f32 "
        "{%0,%1,%2,%3},{%4,%5,%6,%7},{%8,%9},{%0,%1,%2,%3};"
        : "+f"(d[0]), "+f"(d[1]), "+f"(d[2]), "+f"(d[3])
        : "r"(a[0]), "r"(a[1]), "r"(a[2]), "r"(a[3]), "r"(b[0]), "r"(b[1]));
}

// ---------------------------------------------------------------------------
// Kernel A: conv+silu -> qk ; gate scalars i_g, f_g, m_new
// ---------------------------------------------------------------------------
__global__ void kA(const float* __restrict__ x, const float* __restrict__ m,
                   const float* __restrict__ cw, const float* __restrict__ cb,
                   const float* __restrict__ Wi, const float* __restrict__ bi,
                   const float* __restrict__ Wf, const float* __restrict__ bf,
                   float* __restrict__ m_out)
{
    __shared__ float xs[HH];
    __shared__ float si[8], sf[8];
    int b = blockIdx.x, t = threadIdx.x;

    ((float4*)xs)[t] = ((const float4*)(x + b * HH))[t];
    __syncthreads();

    float c0 = cw[0], c1 = cw[1], c2 = cw[2], c3 = cw[3], cbv = cb[0];
    float pi = 0.f, pf = 0.f;
#pragma unroll
    for (int j = 0; j < 4; j++) {
        int w = t * 4 + j;
        // SAME pad for K=4: pad_lo=1, pad_hi=2 ; correlation (no flip)
        float v = cbv + xs[w] * c1;
        if (w >= 1)      v += xs[w - 1] * c0;
        if (w + 1 < HH)  v += xs[w + 1] * c2;
        if (w + 2 < HH)  v += xs[w + 2] * c3;
        float s = v / (1.f + expf(-v));   // silu
        g_qk[b * HH + w] = s;
        pi += xs[w] * Wi[w];
        pf += xs[w] * Wf[w];
    }
#pragma unroll
    for (int o = 16; o; o >>= 1) {
        pi += __shfl_down_sync(~0u, pi, o);
        pf += __shfl_down_sync(~0u, pf, o);
    }
    if ((t & 31) == 0) { si[t >> 5] = pi; sf[t >> 5] = pf; }
    __syncthreads();
    if (t == 0) {
        float it = bi[0], ft = bf[0];
#pragma unroll
        for (int w = 0; w < 8; w++) { it += si[w]; ft += sf[w]; }
        float mb = m[b];
        float mn = fmaxf(ft + mb, it);
        g_ig[b] = expf(it - mn);
        g_fg[b] = expf(ft + mb - mn);
        m_out[b] = mn;
    }
}

// ---------------------------------------------------------------------------
// Kernel B: 5 GEMMs via tf32 mma.sync. BM=64 BN=64 BK=32, split-K=8.
// 128 threads (4 warps in 2x2), warp tile 32x32 (2x4 m16n8k8 per k-step).
// grid: (16, 8, 5) = 640 blocks
// ---------------------------------------------------------------------------
__global__ void kGEMM(const float* __restrict__ x,
                      const float* __restrict__ Wq, const float* __restrict__ Wk,
                      const float* __restrict__ Wv, const float* __restrict__ Wo,
                      const float* __restrict__ Ws)
{
    const int z = blockIdx.z, kz = blockIdx.y;
    const float* A = (z == 2 || z == 3) ? x : g_qk;
    const float* W = (z == 0) ? Wq : (z == 1) ? Wk : (z == 2) ? Wv : (z == 3) ? Wo : Ws;
    const int nt = blockIdx.x * 64;
    const int t = threadIdx.x;
    const int lane = t & 31, warp = t >> 5;
    const int wm = (warp >> 1) * 32;     // warp row base
    const int wn = (warp & 1) * 32;      // warp col base
    const int gr = lane >> 2, c4 = lane & 3;

    __shared__ float As[64][36];         // [m][k] pad->frag banks 4*gr+c4 (bijective)
    __shared__ float Bs[32][72];         // [k][n] pad->frag banks 8*c4+gr (bijective)

    float acc[2][4][4] = {};

    const int kbeg = kz * (HH / SK), kend = kbeg + (HH / SK);
    for (int kt = kbeg; kt < kend; kt += 32) {
        // fill As: 64x32 floats = 512 float4 / 128 thr (cvt to tf32 bits)
#pragma unroll
        for (int i = 0; i < 4; i++) {
            int f = t + i * 128;
            int row = f >> 3, kc = (f & 7) * 4;
            float4 v = *(const float4*)(A + row * HH + kt + kc);
            As[row][kc + 0] = __uint_as_float(f2tf(v.x));
            As[row][kc + 1] = __uint_as_float(f2tf(v.y));
            As[row][kc + 2] = __uint_as_float(f2tf(v.z));
            As[row][kc + 3] = __uint_as_float(f2tf(v.w));
        }
        // fill Bs: 32x64 = 512 float4 / 128 thr
#pragma unroll
        for (int i = 0; i < 4; i++) {
            int f = t + i * 128;
            int kr = f >> 4, nc = (f & 15) * 4;
            float4 v = *(const float4*)(W + (size_t)(kt + kr) * HH + nt + nc);
            float4 w4;
            w4.x = __uint_as_float(f2tf(v.x));
            w4.y = __uint_as_float(f2tf(v.y));
            w4.z = __uint_as_float(f2tf(v.z));
            w4.w = __uint_as_float(f2tf(v.w));
            *(float4*)&Bs[kr][nc] = w4;  // base 288B*kr + 16B*nc/4 -> 16B aligned
        }
        __syncthreads();
#pragma unroll
        for (int kk = 0; kk < 32; kk += 8) {
            unsigned a[2][4], bf2[4][2];
#pragma unroll
            for (int mi = 0; mi < 2; mi++) {
                int r0 = wm + mi * 16 + gr;
                a[mi][0] = __float_as_uint(As[r0][kk + c4]);
                a[mi][1] = __float_as_uint(As[r0 + 8][kk + c4]);
                a[mi][2] = __float_as_uint(As[r0][kk + c4 + 4]);
                a[mi][3] = __float_as_uint(As[r0 + 8][kk + c4 + 4]);
            }
#pragma unroll
            for (int ni = 0; ni < 4; ni++) {
                int ncol = wn + ni * 8 + gr;
                bf2[ni][0] = __float_as_uint(Bs[kk + c4][ncol]);
                bf2[ni][1] = __float_as_uint(Bs[kk + c4 + 4][ncol]);
            }
#pragma unroll
            for (int mi = 0; mi < 2; mi++)
#pragma unroll
                for (int ni = 0; ni < 4; ni++)
                    mma_tf32(acc[mi][ni], a[mi], bf2[ni]);
        }
        __syncthreads();
    }

    float* P = g_part + (size_t)(kz * 5 + z) * BH;
#pragma unroll
    for (int mi = 0; mi < 2; mi++) {
        int row = wm + mi * 16 + gr;
#pragma unroll
        for (int ni = 0; ni < 4; ni++) {
            int col = nt + wn + ni * 8 + 2 * c4;
            *(float2*)(P + (size_t)row * HH + col) =
                make_float2(acc[mi][ni][0], acc[mi][ni][1]);
            *(float2*)(P + (size_t)(row + 8) * HH + col) =
                make_float2(acc[mi][ni][2], acc[mi][ni][3]);
        }
    }
}

// ---------------------------------------------------------------------------
// Epilogue: sum SK partials + bias + activation -> g_act. One block per (z,b)
// row. z==1 blocks also: write n_new, recompute q from partials, reduce
// k.q and n.q -> g_scaler[b]. grid: 320 blocks x 256 thr
// ---------------------------------------------------------------------------
__global__ void kEpi(const float* __restrict__ bq, const float* __restrict__ bk,
                     const float* __restrict__ bv, const float* __restrict__ bo,
                     const float* __restrict__ bs,
                     const float* __restrict__ n, float* __restrict__ out)
{
    __shared__ float red[16];
    int idx = blockIdx.x * 256 + threadIdx.x;   // float4 index
    int e = idx * 4;
    int z = e >> 16;
    int i = e & (BH - 1);
    int col = i & (HH - 1);
    int b = i >> 10;
    const float* bias = (z == 0) ? bq : (z == 1) ? bk : (z == 2) ? bv : (z == 3) ? bo : bs;

    float4 v = *(const float4*)(g_part + (size_t)z * BH + i);
#pragma unroll
    for (int s = 1; s < SK; s++) {
        float4 p = *(const float4*)(g_part + (size_t)(s * 5 + z) * BH + i);
        v.x += p.x; v.y += p.y; v.z += p.z; v.w += p.w;
    }
    float4 bb = *(const float4*)(bias + col);
    v.x += bb.x; v.y += bb.y; v.z += bb.z; v.w += bb.w;
    if (z == 1) { v.x *= 0.03125f; v.y *= 0.03125f; v.z *= 0.03125f; v.w *= 0.03125f; }
    if (z == 3) {
        v.x = 1.f / (1.f + expf(-v.x)); v.y = 1.f / (1.f + expf(-v.y));
        v.z = 1.f / (1.f + expf(-v.z)); v.w = 1.f / (1.f + expf(-v.w));
    }
    *(float4*)(g_act + (size_t)z * BH + i) = v;

    if (z == 1) {
        float fg = g_fg[b], ig = g_ig[b];
        float4 n4 = *(const float4*)(n + i);
        float4 nn;
        nn.x = fg * n4.x + ig * v.x;
        nn.y = fg * n4.y + ig * v.y;
        nn.z = fg * n4.z + ig * v.z;
        nn.w = fg * n4.w + ig * v.w;
        *(float4*)(out + OFF_N + i) = nn;

        // recompute query for this position (deterministic, no race with z==0)
        float4 q = make_float4(0.f, 0.f, 0.f, 0.f);
#pragma unroll
        for (int s = 0; s < SK; s++) {
            float4 p = *(const float4*)(g_part + (size_t)(s * 5) * BH + i);
            q.x += p.x; q.y += p.y; q.z += p.z; q.w += p.w;
        }
        float4 qb = *(const float4*)(bq + col);
        q.x += qb.x; q.y += qb.y; q.z += qb.z; q.w += qb.w;

        float pkq = v.x * q.x + v.y * q.y + v.z * q.z + v.w * q.w;
        float pnq = n4.x * q.x + n4.y * q.y + n4.z * q.z + n4.w * q.w;
        int lane = threadIdx.x & 31, wid = threadIdx.x >> 5;
#pragma unroll
        for (int o = 16; o; o >>= 1) {
            pkq += __shfl_xor_sync(~0u, pkq, o);
            pnq += __shfl_xor_sync(~0u, pnq, o);
        }
        if (lane == 0) { red[wid] = pkq; red[8 + wid] = pnq; }
        __syncthreads();
        if (threadIdx.x == 0) {
            float kq = 0.f, nq = 0.f;
#pragma unroll
            for (int w = 0; w < 8; w++) { kq += red[w]; nq += red[8 + w]; }
            g_scaler[b] = 1.f / fmaxf(fabsf(fg * nq + ig * kq), 1.f);
        }
    }
}

// ---------------------------------------------------------------------------
// Kernel D: HBM-bound pass. 2 rows per warp (shared k/q smem reads),
// 16 rows per block. c_new = f_g*c + (i_g*v_i)*k ; acc_i = c_new_i.q ;
// h_i = out_i*acc_i*scaler + skip_i.  grid: (64, 64), block 256
// ---------------------------------------------------------------------------
__global__ void __launch_bounds__(256, 4)
kD(const float* __restrict__ c, float* __restrict__ out)
{
    __shared__ float ks[HH];
    __shared__ float qs[HH];
    int rb = blockIdx.x, b = blockIdx.y;
    int t = threadIdx.x, lane = t & 31, wid = t >> 5;

    ((float4*)ks)[t] = ((const float4*)(g_act + 1 * BH + b * HH))[t];
    ((float4*)qs)[t] = ((const float4*)(g_act + 0 * BH + b * HH))[t];
    __syncthreads();

    float fg = g_fg[b], ig = g_ig[b], sc = g_scaler[b];

    const int i0 = rb * 16 + wid * 2;
    const int i1 = i0 + 1;
    const size_t base0 = ((size_t)b * HH + i0) * (size_t)HH;
    const size_t base1 = base0 + HH;
    const float igv0 = ig * g_act[2 * BH + b * HH + i0];
    const float igv1 = ig * g_act[2 * BH + b * HH + i1];
    float acc0 = 0.f, acc1 = 0.f;

#pragma unroll
    for (int ch = 0; ch < 8; ch += 2) {
        int ka = ch * 128 + lane * 4;
        int kb2 = ka + 128;
        float4 c00 = __ldcs((const float4*)(c + base0 + ka));
        float4 c10 = __ldcs((const float4*)(c + base1 + ka));
        float4 c01 = __ldcs((const float4*)(c + base0 + kb2));
        float4 c11 = __ldcs((const float4*)(c + base1 + kb2));
        float4 k0 = *(float4*)(ks + ka), q0 = *(float4*)(qs + ka);
        float4 k1 = *(float4*)(ks + kb2), q1 = *(float4*)(qs + kb2);
        float4 r;
        r.x = fg * c00.x + igv0 * k0.x; r.y = fg * c00.y + igv0 * k0.y;
        r.z = fg * c00.z + igv0 * k0.z; r.w = fg * c00.w + igv0 * k0.w;
        __stcs((float4*)(out + base0 + ka), r);
        acc0 += r.x * q0.x + r.y * q0.y + r.z * q0.z + r.w * q0.w;
        r.x = fg * c10.x + igv1 * k0.x; r.y = fg * c10.y + igv1 * k0.y;
        r.z = fg * c10.z + igv1 * k0.z; r.w = fg * c10.w + igv1 * k0.w;
        __stcs((float4*)(out + base1 + ka), r);
        acc1 += r.x * q0.x + r.y * q0.y + r.z * q0.z + r.w * q0.w;
        r.x = fg * c01.x + igv0 * k1.x; r.y = fg * c01.y + igv0 * k1.y;
        r.z = fg * c01.z + igv0 * k1.z; r.w = fg * c01.w + igv0 * k1.w;
        __stcs((float4*)(out + base0 + kb2), r);
        acc0 += r.x * q1.x + r.y * q1.y + r.z * q1.z + r.w * q1.w;
        r.x = fg * c11.x + igv1 * k1.x; r.y = fg * c11.y + igv1 * k1.y;
        r.z = fg * c11.z + igv1 * k1.z; r.w = fg * c11.w + igv1 * k1.w;
        __stcs((float4*)(out + base1 + kb2), r);
        acc1 += r.x * q1.x + r.y * q1.y + r.z * q1.z + r.w * q1.w;
    }
#pragma unroll
    for (int o = 16; o; o >>= 1) {
        acc0 += __shfl_xor_sync(~0u, acc0, o);
        acc1 += __shfl_xor_sync(~0u, acc1, o);
    }
    if (lane == 0) {
        out[OFF_H + (size_t)b * HH + i0] =
            g_act[3 * BH + b * HH + i0] * (acc0 * sc) + g_act[4 * BH + b * HH + i0];
        out[OFF_H + (size_t)b * HH + i1] =
            g_act[3 * BH + b * HH + i1] * (acc1 * sc) + g_act[4 * BH + b * HH + i1];
    }
}

// ---------------------------------------------------------------------------
extern "C" void kernel_launch(void* const* d_in, const int* in_sizes, int n_in,
                              void* d_out, int out_size)
{
    (void)in_sizes; (void)n_in; (void)out_size;
    const float* c      = (const float*)d_in[0];
    const float* n      = (const float*)d_in[1];
    const float* m      = (const float*)d_in[2];
    const float* x      = (const float*)d_in[3];
    const float* Wq     = (const float*)d_in[4];
    const float* bq     = (const float*)d_in[5];
    const float* Wk     = (const float*)d_in[6];
    const float* bk     = (const float*)d_in[7];
    const float* Wv     = (const float*)d_in[8];
    const float* bv     = (const float*)d_in[9];
    const float* conv_w = (const float*)d_in[10];
    const float* conv_b = (const float*)d_in[11];
    const float* Wi     = (const float*)d_in[12];
    const float* bi     = (const float*)d_in[13];
    const float* Wf     = (const float*)d_in[14];
    const float* bf     = (const float*)d_in[15];
    const float* Wo     = (const float*)d_in[16];
    const float* bo     = (const float*)d_in[17];
    const float* Wskip  = (const float*)d_in[18];
    const float* bskip  = (const float*)d_in[19];
    float* out = (float*)d_out;

    kA<<<BB, 256>>>(x, m, conv_w, conv_b, Wi, bi, Wf, bf, out + OFF_M);
    kGEMM<<<dim3(16, SK, 5), 128>>>(x, Wq, Wk, Wv, Wo, Wskip);
    kEpi<<<320, 256>>>(bq, bk, bv, bo, bskip, n, out);
    kD<<<dim3(64, 64), 256>>>(c, out);
}